// round 2
// baseline (speedup 1.0000x reference)
#include <cuda_runtime.h>
#include <cuda_bf16.h>

#define FDIM 128
#define SNEI 10
#define KCLU 16
#define EDIM 128
#define NJOBS 197          // 1 + 10 + 10 + 16 + 160
#define NBATCH 7           // ceil(197/32) batches of 32

// scratch for combined features [B x 256]
__device__ float g_comb[20480 * 256];

// ---------------------------------------------------------------------------
// Kernel A: per-row irregular part -> combined[b, 0:128]=self, [128:256]=agg
// 128 threads per block, thread = feature index f.
// ---------------------------------------------------------------------------
__global__ __launch_bounds__(128, 4)
void row_kernel(const int* __restrict__ nodes,
                const int* __restrict__ neigh_idx,
                const float* __restrict__ self_table,
                const float* __restrict__ neigh_table,
                const float* __restrict__ center,
                const float* __restrict__ cmask,
                const float* __restrict__ alpha,
                float* __restrict__ comb,
                int B)
{
    int b = blockIdx.x;
    if (b >= B) return;
    int f    = threadIdx.x;       // 0..127
    int lane = f & 31;
    int warp = f >> 5;

    __shared__ float red[4][NBATCH * 32];   // per-warp partial sums (4*224)
    __shared__ float res[NBATCH * 32];      // combined sums
    __shared__ float qsm[SNEI * KCLU];      // q[s][k]

    // ---- gathers (coalesced across f) ----
    int node = nodes[b];
    float sf = self_table[(size_t)node * FDIM + f];

    float nb[SNEI];
#pragma unroll
    for (int s = 0; s < SNEI; s++) {
        int idx = neigh_idx[b * SNEI + s];
        nb[s] = neigh_table[(size_t)idx * FDIM + f];
    }
    float a_s = alpha[f];
    float a_n = alpha[FDIM + f];

    float cen[KCLU];
#pragma unroll
    for (int k = 0; k < KCLU; k++) cen[k] = center[k * FDIM + f];

    // ---- 197 block-wide dot products via batched butterfly multi-reduce ----
    // job layout: 0: self.a_self | 1..10: nb[s].a_neigh | 11..20: n2[s]
    //             21..36: c2[k]  | 37..196: cross[s*16+k]
#pragma unroll
    for (int m = 0; m < NBATCH; m++) {
        float v[32];
#pragma unroll
        for (int j = 0; j < 32; j++) {
            int job = m * 32 + j;
            float p;
            if (job == 0)        p = sf * a_s;
            else if (job < 11)   p = nb[job - 1] * a_n;
            else if (job < 21) { float x = nb[job - 11]; p = x * x; }
            else if (job < 37) { float c = cen[job - 21]; p = c * c; }
            else if (job < NJOBS) {
                int t = job - 37;
                p = nb[t >> 4] * cen[t & 15];
            } else p = 0.0f;
            v[j] = p;
        }
        // multi-reduce: after this, lane L's v[0] = sum over lanes of value L
#pragma unroll
        for (int o = 16; o > 0; o >>= 1) {
#pragma unroll
            for (int j = 0; j < o; j++) {
                float give = (lane & o) ? v[j] : v[j + o];
                float got  = __shfl_xor_sync(0xffffffffu, give, o);
                float keep = (lane & o) ? v[j + o] : v[j];
                v[j] = keep + got;
            }
        }
        red[warp][m * 32 + lane] = v[0];
    }
    __syncthreads();

    // combine 4 warps
    for (int j = f; j < NBATCH * 32; j += 128)
        res[j] = red[0][j] + red[1][j] + red[2][j] + red[3][j];
    __syncthreads();

    // ---- q[s][k] = 1/(n2 - 2 cross + c2 + 1) (computed once) ----
    for (int t = f; t < SNEI * KCLU; t += 128) {
        int s = t >> 4, k = t & 15;
        float denom = res[11 + s] - 2.0f * res[37 + t] + res[21 + k] + 1.0f;
        qsm[t] = 1.0f / denom;
    }
    __syncthreads();

    // ---- attention weights (cheap; computed redundantly per thread) ----
    float d_self = res[0];
    float attn[SNEI];
    float asum = 0.0f;
#pragma unroll
    for (int s = 0; s < SNEI; s++) {
        float l = d_self + res[1 + s];
        l = fmaxf(l, 0.0f);
        float e = __expf(l);
        attn[s] = e;
        asum += e;
    }
    float inv_asum = 1.0f / asum;

    // ---- coef + aggregate ----
    float msk[KCLU];
#pragma unroll
    for (int k = 0; k < KCLU; k++) msk[k] = cmask[k * FDIM + f];

    float agg = 0.0f;
#pragma unroll
    for (int s = 0; s < SNEI; s++) {
        float c = 0.0f;
#pragma unroll
        for (int k = 0; k < KCLU; k++)
            c = fmaf(qsm[s * KCLU + k], msk[k], c);
        agg = fmaf(attn[s] * inv_asum * nb[s], c, agg);
    }

    comb[(size_t)b * 256 + f]        = sf;
    comb[(size_t)b * 256 + 128 + f]  = agg;
}

// ---------------------------------------------------------------------------
// Kernel B: out[b][e] = relu( sum_j comb[b][j] * W[e][j] ),  (B x 256)@(256 x 128)
// Tiled SGEMM: BM=64, BN=128, BK=16, 256 threads, 4x8 register tile.
// ---------------------------------------------------------------------------
#define BM 64
#define BN 128
#define BK 16

__global__ __launch_bounds__(256)
void gemm_relu_kernel(const float* __restrict__ A,   // B x 256
                      const float* __restrict__ W,   // 128 x 256
                      float* __restrict__ out,       // B x 128
                      int Brows)
{
    __shared__ __align__(16) float As[BK][BM];
    __shared__ __align__(16) float Bs[BK][BN];

    int tid = threadIdx.x;
    int tx  = tid & 15;        // 16 col groups of 8 -> 128 cols
    int ty  = tid >> 4;        // 16 row groups of 4 -> 64 rows
    int row0 = blockIdx.x * BM;

    float acc[4][8];
#pragma unroll
    for (int i = 0; i < 4; i++)
#pragma unroll
        for (int j = 0; j < 8; j++) acc[i][j] = 0.0f;

    for (int k0 = 0; k0 < 256; k0 += BK) {
        // load A tile (64 x 16): one float4 per thread
        {
            int r  = tid >> 2;           // 0..63
            int c4 = (tid & 3) * 4;      // 0,4,8,12
            int grow = row0 + r;
            float4 av = make_float4(0.f, 0.f, 0.f, 0.f);
            if (grow < Brows)
                av = *(const float4*)&A[(size_t)grow * 256 + k0 + c4];
            As[c4 + 0][r] = av.x;
            As[c4 + 1][r] = av.y;
            As[c4 + 2][r] = av.z;
            As[c4 + 3][r] = av.w;
        }
        // load B tile (128 x 16 of W, transposed into Bs[k][n]): two float4 per thread
        {
            int n  = tid >> 1;           // 0..127
            int c4 = (tid & 1) * 8;      // 0 or 8
            float4 b0 = *(const float4*)&W[(size_t)n * 256 + k0 + c4];
            float4 b1 = *(const float4*)&W[(size_t)n * 256 + k0 + c4 + 4];
            Bs[c4 + 0][n] = b0.x;
            Bs[c4 + 1][n] = b0.y;
            Bs[c4 + 2][n] = b0.z;
            Bs[c4 + 3][n] = b0.w;
            Bs[c4 + 4][n] = b1.x;
            Bs[c4 + 5][n] = b1.y;
            Bs[c4 + 6][n] = b1.z;
            Bs[c4 + 7][n] = b1.w;
        }
        __syncthreads();

#pragma unroll
        for (int kk = 0; kk < BK; kk++) {
            float4 a4 = *(const float4*)&As[kk][ty * 4];
            float4 b4 = *(const float4*)&Bs[kk][tx * 8];
            float4 b5 = *(const float4*)&Bs[kk][tx * 8 + 4];
            float a[4] = {a4.x, a4.y, a4.z, a4.w};
            float bb[8] = {b4.x, b4.y, b4.z, b4.w, b5.x, b5.y, b5.z, b5.w};
#pragma unroll
            for (int i = 0; i < 4; i++)
#pragma unroll
                for (int j = 0; j < 8; j++)
                    acc[i][j] = fmaf(a[i], bb[j], acc[i][j]);
        }
        __syncthreads();
    }

    // write with relu
#pragma unroll
    for (int i = 0; i < 4; i++) {
        int grow = row0 + ty * 4 + i;
        if (grow < Brows) {
            float4 o0, o1;
            o0.x = fmaxf(acc[i][0], 0.f); o0.y = fmaxf(acc[i][1], 0.f);
            o0.z = fmaxf(acc[i][2], 0.f); o0.w = fmaxf(acc[i][3], 0.f);
            o1.x = fmaxf(acc[i][4], 0.f); o1.y = fmaxf(acc[i][5], 0.f);
            o1.z = fmaxf(acc[i][6], 0.f); o1.w = fmaxf(acc[i][7], 0.f);
            *(float4*)&out[(size_t)grow * EDIM + tx * 8]     = o0;
            *(float4*)&out[(size_t)grow * EDIM + tx * 8 + 4] = o1;
        }
    }
}

// ---------------------------------------------------------------------------
extern "C" void kernel_launch(void* const* d_in, const int* in_sizes, int n_in,
                              void* d_out, int out_size)
{
    const int*   nodes      = (const int*)d_in[0];
    const int*   neigh_idx  = (const int*)d_in[1];
    const float* self_table = (const float*)d_in[2];
    const float* neigh_tab  = (const float*)d_in[3];
    const float* center     = (const float*)d_in[4];
    const float* cmask      = (const float*)d_in[5];
    const float* weight     = (const float*)d_in[6];
    const float* alpha      = (const float*)d_in[7];
    float*       out        = (float*)d_out;

    int B = in_sizes[0];

    float* comb = nullptr;
    cudaGetSymbolAddress((void**)&comb, g_comb);

    row_kernel<<<B, 128>>>(nodes, neigh_idx, self_table, neigh_tab,
                           center, cmask, alpha, comb, B);

    int gblocks = (B + BM - 1) / BM;
    gemm_relu_kernel<<<gblocks, 256>>>(comb, weight, out, B);
}

// round 3
// speedup vs baseline: 1.2181x; 1.2181x over previous
#include <cuda_runtime.h>
#include <cuda_bf16.h>

#define FDIM 128
#define SNEI 10
#define KCLU 16

// scratch (allocation-free rule: __device__ globals)
__device__ float g_comb[20480 * 256];      // [B x 256] combined features
__device__ float g_pv[200064 * 16];        // per-node: n2 - 2*cross[k] + 1
__device__ float g_pdot[200064];           // per-node: neigh . a_neigh
__device__ float g_c2[16];                 // per-cluster: |center_k|^2

// packed f32x2 helpers (sm_100+)
#define FFMA2(d, a, b, c) \
    asm("fma.rn.f32x2 %0, %1, %2, %3;" : "=l"(d) : "l"(a), "l"(b), "l"(c))
#define PACK2(d, lo, hi) \
    asm("mov.b64 %0, {%1, %2};" : "=l"(d) : "f"(lo), "f"(hi))
#define UNPACK2(lo, hi, v) \
    asm("mov.b64 {%0, %1}, %2;" : "=f"(lo), "=f"(hi) : "l"(v))

// ---------------------------------------------------------------------------
// c2[k] = sum_f center[k][f]^2   (one tiny block)
// ---------------------------------------------------------------------------
__global__ void c2_kernel(const float* __restrict__ center, float* __restrict__ c2)
{
    int w = threadIdx.x >> 5, l = threadIdx.x & 31;  // 16 warps
    float4 v = ((const float4*)center)[w * 32 + l];
    float s = v.x * v.x + v.y * v.y + v.z * v.z + v.w * v.w;
#pragma unroll
    for (int o = 16; o; o >>= 1) s += __shfl_xor_sync(0xffffffffu, s, o);
    if (l == 0) c2[w] = s;
}

// ---------------------------------------------------------------------------
// Precompute per node: pv[n][k] = n2 - 2*cross[n][k] + 1, pdot[n] = row.a_neigh
// 64 threads, 64 nodes per block; rows staged in smem (stride 129 = no bank
// conflicts), center read as broadcast LDS.128, math in packed f32x2.
// ---------------------------------------------------------------------------
__global__ __launch_bounds__(64)
void precompute_kernel(const float* __restrict__ neigh_table,
                       const float* __restrict__ center,
                       const float* __restrict__ alpha,
                       float* __restrict__ pv,
                       float* __restrict__ pdot,
                       int N)
{
    __shared__ float rows_s[64 * 129];
    __shared__ __align__(16) float cen_s[16 * 128];
    __shared__ __align__(16) float alp_s[128];

    int t = threadIdx.x;              // 0..63
    int base = blockIdx.x * 64;

    for (int i = t; i < 512; i += 64)
        ((float4*)cen_s)[i] = ((const float4*)center)[i];
    if (t < 32)
        ((float4*)alp_s)[t] = ((const float4*)alpha)[32 + t];  // alpha[128:256]

    // coalesced load of 64 rows into padded smem
#pragma unroll
    for (int j = 0; j < 32; j++) {
        int i = j * 64 + t;           // float4 index over the 64x128 tile
        int r = i >> 5, c = i & 31;
        float4 v = make_float4(0.f, 0.f, 0.f, 0.f);
        if (base + r < N)
            v = ((const float4*)neigh_table)[(size_t)(base + r) * 32 + c];
        float* dst = &rows_s[r * 129 + c * 4];
        dst[0] = v.x; dst[1] = v.y; dst[2] = v.z; dst[3] = v.w;
    }
    __syncthreads();

    if (base + t >= N) return;

    unsigned long long crp[16], n2p = 0ull, adp = 0ull;
#pragma unroll
    for (int k = 0; k < 16; k++) crp[k] = 0ull;

    const float* row = &rows_s[t * 129];
#pragma unroll 4
    for (int q = 0; q < 32; q++) {
        float x0 = row[q * 4 + 0], x1 = row[q * 4 + 1];
        float x2 = row[q * 4 + 2], x3 = row[q * 4 + 3];
        unsigned long long xp0, xp1;
        PACK2(xp0, x0, x1);
        PACK2(xp1, x2, x3);
        ulonglong2 ap = ((const ulonglong2*)alp_s)[q];   // broadcast
        FFMA2(adp, xp0, ap.x, adp);
        FFMA2(adp, xp1, ap.y, adp);
        FFMA2(n2p, xp0, xp0, n2p);
        FFMA2(n2p, xp1, xp1, n2p);
#pragma unroll
        for (int k = 0; k < 16; k++) {
            ulonglong2 cp = ((const ulonglong2*)(cen_s + k * 128))[q];  // broadcast
            FFMA2(crp[k], xp0, cp.x, crp[k]);
            FFMA2(crp[k], xp1, cp.y, crp[k]);
        }
    }

    float n2lo, n2hi, adlo, adhi;
    UNPACK2(n2lo, n2hi, n2p);
    UNPACK2(adlo, adhi, adp);
    float basev = (n2lo + n2hi) + 1.0f;

    float outv[16];
#pragma unroll
    for (int k = 0; k < 16; k++) {
        float lo, hi; UNPACK2(lo, hi, crp[k]);
        outv[k] = fmaf(-2.0f, lo + hi, basev);
    }
    float4* dst = (float4*)&pv[(size_t)(base + t) * 16];
#pragma unroll
    for (int kp = 0; kp < 4; kp++)
        dst[kp] = make_float4(outv[kp*4], outv[kp*4+1], outv[kp*4+2], outv[kp*4+3]);
    pdot[base + t] = adlo + adhi;
}

// ---------------------------------------------------------------------------
// Row kernel: gathers + q + attention + coef + aggregate -> comb[b][0:256]
// 128 threads, thread = feature. No block-wide reductions except d_self.
// ---------------------------------------------------------------------------
__global__ __launch_bounds__(128)
void row_kernel(const int* __restrict__ nodes,
                const int* __restrict__ neigh_idx,
                const float* __restrict__ self_table,
                const float* __restrict__ neigh_table,
                const float* __restrict__ cmask,
                const float* __restrict__ alpha,
                const float* __restrict__ pv,
                const float* __restrict__ pdot,
                const float* __restrict__ c2,
                float* __restrict__ comb,
                int B)
{
    int b = blockIdx.x;
    if (b >= B) return;
    int f = threadIdx.x, lane = f & 31, warp = f >> 5;

    __shared__ int   idx_s[SNEI];
    __shared__ int   node_s;
    __shared__ float pdot_s[SNEI];
    __shared__ float c2_s[16];
    __shared__ __align__(8) float q_s[SNEI * 16];
    __shared__ float wsum[4];

    if (f < SNEI) idx_s[f] = neigh_idx[b * SNEI + f];
    if (f == SNEI) node_s = nodes[b];
    if (f >= 32 && f < 48) c2_s[f - 32] = c2[f - 32];
    __syncthreads();

    float sf = self_table[(size_t)node_s * FDIM + f];
    float nb[SNEI];
#pragma unroll
    for (int s = 0; s < SNEI; s++)
        nb[s] = neigh_table[(size_t)idx_s[s] * FDIM + f];

    // q[s][k] = 1 / (pv[idx_s[s]][k] + c2[k])
    {
        int t = f;
        if (t < SNEI * 16) {
            float d = pv[(size_t)idx_s[t >> 4] * 16 + (t & 15)] + c2_s[t & 15];
            q_s[t] = 1.0f / d;
        }
        t = f + 128;
        if (t < SNEI * 16) {
            float d = pv[(size_t)idx_s[t >> 4] * 16 + (t & 15)] + c2_s[t & 15];
            q_s[t] = 1.0f / d;
        }
        if (f >= 64 && f < 64 + SNEI) pdot_s[f - 64] = pdot[idx_s[f - 64]];
    }

    // d_self = sum_f sf * alpha[f]  (block reduce)
    float v = sf * alpha[f];
#pragma unroll
    for (int o = 16; o; o >>= 1) v += __shfl_xor_sync(0xffffffffu, v, o);
    if (lane == 0) wsum[warp] = v;
    __syncthreads();
    float d_self = wsum[0] + wsum[1] + wsum[2] + wsum[3];

    // attention weights (redundant per thread, tiny)
    float attn[SNEI], asum = 0.f;
#pragma unroll
    for (int s = 0; s < SNEI; s++) {
        float l = fmaxf(d_self + pdot_s[s], 0.f);
        float e = __expf(l);
        attn[s] = e;
        asum += e;
    }
    float inv = 1.0f / asum;

    // coef[s] = sum_k q[s][k]*mask[k][f], packed over k-pairs
    unsigned long long mp[8];
#pragma unroll
    for (int kp = 0; kp < 8; kp++) {
        float m0 = cmask[(2 * kp) * FDIM + f];
        float m1 = cmask[(2 * kp + 1) * FDIM + f];
        PACK2(mp[kp], m0, m1);
    }
    float agg = 0.f;
#pragma unroll
    for (int s = 0; s < SNEI; s++) {
        unsigned long long cacc = 0ull;
        const unsigned long long* qp = (const unsigned long long*)&q_s[s * 16];
#pragma unroll
        for (int kp = 0; kp < 8; kp++)
            FFMA2(cacc, qp[kp], mp[kp], cacc);
        float lo, hi; UNPACK2(lo, hi, cacc);
        agg = fmaf(attn[s] * inv * nb[s], lo + hi, agg);
    }

    comb[(size_t)b * 256 + f]       = sf;
    comb[(size_t)b * 256 + 128 + f] = agg;
}

// ---------------------------------------------------------------------------
// GEMM + ReLU: out(B x 128) = relu(comb(B x 256) @ W^T), W is 128 x 256.
// BM=64, BN=128, BK=16, 128 threads, 8x8 microtile, packed f32x2 accumulators.
// ---------------------------------------------------------------------------
#define GBM 64
#define GBN 128
#define GBK 16

__global__ __launch_bounds__(128)
void gemm_relu_kernel(const float* __restrict__ A,
                      const float* __restrict__ W,
                      float* __restrict__ out,
                      int Brows)
{
    __shared__ __align__(16) float As[GBK][GBM];
    __shared__ __align__(16) float Bs[GBK][GBN];

    int tid = threadIdx.x;
    int tx = tid & 15;       // col group: 8 cols each -> 128
    int ty = tid >> 4;       // row group: 8 rows each -> 64
    int row0 = blockIdx.x * GBM;

    unsigned long long acc[8][4];
#pragma unroll
    for (int i = 0; i < 8; i++)
#pragma unroll
        for (int p = 0; p < 4; p++) acc[i][p] = 0ull;

    for (int k0 = 0; k0 < 256; k0 += GBK) {
        // A tile 64x16 (transposed into As[k][m])
#pragma unroll
        for (int j = 0; j < 2; j++) {
            int i = j * 128 + tid;
            int r = i >> 2, c4 = (i & 3) * 4;
            float4 v = make_float4(0.f, 0.f, 0.f, 0.f);
            if (row0 + r < Brows)
                v = *(const float4*)&A[(size_t)(row0 + r) * 256 + k0 + c4];
            As[c4 + 0][r] = v.x; As[c4 + 1][r] = v.y;
            As[c4 + 2][r] = v.z; As[c4 + 3][r] = v.w;
        }
        // W tile 128x16 (transposed into Bs[k][n])
        {
            int n = tid;
#pragma unroll
            for (int j = 0; j < 4; j++) {
                float4 v = *(const float4*)&W[(size_t)n * 256 + k0 + j * 4];
                Bs[j * 4 + 0][n] = v.x; Bs[j * 4 + 1][n] = v.y;
                Bs[j * 4 + 2][n] = v.z; Bs[j * 4 + 3][n] = v.w;
            }
        }
        __syncthreads();

#pragma unroll
        for (int kk = 0; kk < GBK; kk++) {
            float4 a0 = *(const float4*)&As[kk][ty * 8];
            float4 a1 = *(const float4*)&As[kk][ty * 8 + 4];
            const unsigned long long* bp =
                (const unsigned long long*)&Bs[kk][tx * 8];
            unsigned long long b0 = bp[0], b1 = bp[1], b2 = bp[2], b3 = bp[3];
            float av[8] = {a0.x, a0.y, a0.z, a0.w, a1.x, a1.y, a1.z, a1.w};
#pragma unroll
            for (int i = 0; i < 8; i++) {
                unsigned long long ap;
                PACK2(ap, av[i], av[i]);
                FFMA2(acc[i][0], ap, b0, acc[i][0]);
                FFMA2(acc[i][1], ap, b1, acc[i][1]);
                FFMA2(acc[i][2], ap, b2, acc[i][2]);
                FFMA2(acc[i][3], ap, b3, acc[i][3]);
            }
        }
        __syncthreads();
    }

    // epilogue: relu + store
#pragma unroll
    for (int i = 0; i < 8; i++) {
        int r = row0 + ty * 8 + i;
        if (r < Brows) {
            float o[8];
#pragma unroll
            for (int p = 0; p < 4; p++) {
                float lo, hi; UNPACK2(lo, hi, acc[i][p]);
                o[2 * p]     = fmaxf(lo, 0.f);
                o[2 * p + 1] = fmaxf(hi, 0.f);
            }
            *(float4*)&out[(size_t)r * FDIM + tx * 8]     = make_float4(o[0], o[1], o[2], o[3]);
            *(float4*)&out[(size_t)r * FDIM + tx * 8 + 4] = make_float4(o[4], o[5], o[6], o[7]);
        }
    }
}

// ---------------------------------------------------------------------------
extern "C" void kernel_launch(void* const* d_in, const int* in_sizes, int n_in,
                              void* d_out, int out_size)
{
    const int*   nodes      = (const int*)d_in[0];
    const int*   neigh_idx  = (const int*)d_in[1];
    const float* self_table = (const float*)d_in[2];
    const float* neigh_tab  = (const float*)d_in[3];
    const float* center     = (const float*)d_in[4];
    const float* cmask      = (const float*)d_in[5];
    const float* weight     = (const float*)d_in[6];
    const float* alpha      = (const float*)d_in[7];
    float*       out        = (float*)d_out;

    int B = in_sizes[0];
    int N = in_sizes[3] / FDIM;

    float *comb, *pv, *pd, *c2;
    cudaGetSymbolAddress((void**)&comb, g_comb);
    cudaGetSymbolAddress((void**)&pv,   g_pv);
    cudaGetSymbolAddress((void**)&pd,   g_pdot);
    cudaGetSymbolAddress((void**)&c2,   g_c2);

    c2_kernel<<<1, 512>>>(center, c2);
    precompute_kernel<<<(N + 63) / 64, 64>>>(neigh_tab, center, alpha, pv, pd, N);
    row_kernel<<<B, 128>>>(nodes, neigh_idx, self_table, neigh_tab,
                           cmask, alpha, pv, pd, c2, comb, B);
    gemm_relu_kernel<<<(B + GBM - 1) / GBM, 128>>>(comb, weight, out, B);
}

// round 4
// speedup vs baseline: 1.3353x; 1.0962x over previous
#include <cuda_runtime.h>
#include <cuda_bf16.h>

#define FDIM 128
#define SNEI 10
#define KCLU 16
#define NMAX 200704
#define BMAX 20480

typedef unsigned long long ull;

// scratch (__device__ globals per allocation rules)
__device__ float g_prod[(size_t)NMAX * FDIM];   // neigh[n,f] * coef[n,f]
__device__ float g_pdot[NMAX];                  // neigh[n] . a_neigh
__device__ float g_c2[16];
__device__ float g_comb[(size_t)BMAX * 256];
__device__ float g_part[2 * (size_t)BMAX * FDIM];

#define FFMA2(d, a, b, c) \
    asm("fma.rn.f32x2 %0, %1, %2, %3;" : "=l"(d) : "l"(a), "l"(b), "l"(c))
#define PACK2(d, lo, hi) \
    asm("mov.b64 %0, {%1, %2};" : "=l"(d) : "f"(lo), "f"(hi))
#define UNPACK2(lo, hi, v) \
    asm("mov.b64 {%0, %1}, %2;" : "=f"(lo), "=f"(hi) : "l"(v))

// ---------------------------------------------------------------------------
// c2[k] = |center_k|^2
// ---------------------------------------------------------------------------
__global__ void c2_kernel(const float* __restrict__ center, float* __restrict__ c2)
{
    int w = threadIdx.x >> 5, l = threadIdx.x & 31;  // 16 warps
    float4 v = ((const float4*)center)[w * 32 + l];
    float s = v.x * v.x + v.y * v.y + v.z * v.z + v.w * v.w;
#pragma unroll
    for (int o = 16; o; o >>= 1) s += __shfl_xor_sync(0xffffffffu, s, o);
    if (l == 0) c2[w] = s;
}

// ---------------------------------------------------------------------------
// Precompute per node n:
//   pdot[n]   = row . a_neigh
//   q[n][k]   = 1/(n2 - 2 cross[k] + 1 + c2[k])
//   prod[n,f] = row[f] * sum_k q[n][k] * mask[k][f]
// 64 nodes per block, 128 threads. Phase 2 splits each node's reductions
// across 2 threads (feature halves); phase 3 remaps thread->feature.
// ---------------------------------------------------------------------------
__global__ __launch_bounds__(128)
void precompute_kernel(const float* __restrict__ neigh_table,
                       const float* __restrict__ center,
                       const float* __restrict__ alpha,
                       const float* __restrict__ cmask,
                       const float* __restrict__ c2g,
                       float* __restrict__ prod,
                       float* __restrict__ pdot,
                       int N)
{
    __shared__ float rows_s[64 * 129];                       // 33024 B
    __shared__ __align__(16) float cen_s[16 * 128];          // 8192 B (aliased by partials)
    __shared__ __align__(16) float alp_s[128];               // 512 B
    __shared__ __align__(8)  float q_s[64 * 18];             // 4608 B (stride 18)
    __shared__ float c2_s[16];

    int t = threadIdx.x;
    int base = blockIdx.x * 64;
    int n = t & 63, h = t >> 6;

    // mask registers for phase 3 (thread = feature t)
    ull mp[8];
#pragma unroll
    for (int kp = 0; kp < 8; kp++) {
        float m0 = cmask[(2 * kp) * FDIM + t];
        float m1 = cmask[(2 * kp + 1) * FDIM + t];
        PACK2(mp[kp], m0, m1);
    }

    // stage 64 rows + center + alpha_neigh + c2
#pragma unroll
    for (int j = 0; j < 16; j++) {
        int i = j * 128 + t;                  // float4 index over 64x128 tile
        int r = i >> 5, c = i & 31;
        float4 v = make_float4(0.f, 0.f, 0.f, 0.f);
        if (base + r < N)
            v = ((const float4*)neigh_table)[(size_t)(base + r) * 32 + c];
        float* dst = &rows_s[r * 129 + c * 4];
        dst[0] = v.x; dst[1] = v.y; dst[2] = v.z; dst[3] = v.w;
    }
#pragma unroll
    for (int j = 0; j < 4; j++)
        ((float4*)cen_s)[j * 128 + t] = ((const float4*)center)[j * 128 + t];
    if (t < 32) ((float4*)alp_s)[t] = ((const float4*)alpha)[32 + t];
    if (t < 16) c2_s[t] = c2g[t];
    __syncthreads();

    // phase 2: each thread reduces half the features of node n
    ull crp[16], n2p = 0ull, adp = 0ull;
#pragma unroll
    for (int k = 0; k < 16; k++) crp[k] = 0ull;

    {
        const float* row = &rows_s[n * 129 + h * 64];
#pragma unroll 4
        for (int q = 0; q < 16; q++) {
            float x0 = row[q * 4 + 0], x1 = row[q * 4 + 1];
            float x2 = row[q * 4 + 2], x3 = row[q * 4 + 3];
            ull xp0, xp1;
            PACK2(xp0, x0, x1);
            PACK2(xp1, x2, x3);
            ulonglong2 ap = ((const ulonglong2*)(alp_s + h * 64))[q];
            FFMA2(adp, xp0, ap.x, adp);
            FFMA2(adp, xp1, ap.y, adp);
            FFMA2(n2p, xp0, xp0, n2p);
            FFMA2(n2p, xp1, xp1, n2p);
#pragma unroll
            for (int k = 0; k < 16; k++) {
                ulonglong2 cp = ((const ulonglong2*)(cen_s + k * 128 + h * 64))[q];
                FFMA2(crp[k], xp0, cp.x, crp[k]);
                FFMA2(crp[k], xp1, cp.y, crp[k]);
            }
        }
    }

    float cr[16], n2v, adv;
    {
        float lo, hi;
#pragma unroll
        for (int k = 0; k < 16; k++) { UNPACK2(lo, hi, crp[k]); cr[k] = lo + hi; }
        UNPACK2(lo, hi, n2p); n2v = lo + hi;
        UNPACK2(lo, hi, adp); adv = lo + hi;
    }
    __syncthreads();                 // cen_s free -> reuse as partial buffer
    float* part_s = cen_s;           // 64 nodes x 19 floats (odd stride: no conflicts)
    if (h == 1) {
#pragma unroll
        for (int k = 0; k < 16; k++) part_s[n * 19 + k] = cr[k];
        part_s[n * 19 + 16] = n2v;
        part_s[n * 19 + 17] = adv;
    }
    __syncthreads();
    if (h == 0) {
        float n2t = n2v + part_s[n * 19 + 16];
        float adt = adv + part_s[n * 19 + 17];
        float bse = n2t + 1.0f;
#pragma unroll
        for (int k = 0; k < 16; k++) {
            float crt = cr[k] + part_s[n * 19 + k];
            float den = fmaf(-2.0f, crt, bse + c2_s[k]);
            q_s[n * 18 + k] = 1.0f / den;
        }
        if (base + n < N) pdot[base + n] = adt;
    }
    __syncthreads();

    // phase 3: thread = feature t; loop nodes
    int nlim = min(64, N - base);
    for (int nn = 0; nn < nlim; nn++) {
        const ull* qp = (const ull*)&q_s[nn * 18];
        ull acc = 0ull;
#pragma unroll
        for (int kp = 0; kp < 8; kp++)
            FFMA2(acc, qp[kp], mp[kp], acc);
        float lo, hi; UNPACK2(lo, hi, acc);
        float x = rows_s[nn * 129 + t];
        prod[(size_t)(base + nn) * FDIM + t] = x * (lo + hi);
    }
}

// ---------------------------------------------------------------------------
// Row kernel: warp per row. Gather self + 10 prod rows, attention, aggregate.
// ---------------------------------------------------------------------------
__global__ __launch_bounds__(256)
void row_kernel(const int* __restrict__ nodes,
                const int* __restrict__ neigh_idx,
                const float* __restrict__ self_table,
                const float* __restrict__ alpha,
                const float* __restrict__ pdot,
                const float* __restrict__ prod,
                float* __restrict__ comb,
                int B)
{
    int wid = threadIdx.x >> 5, lane = threadIdx.x & 31;
    int b = blockIdx.x * 8 + wid;
    if (b >= B) return;

    int node = nodes[b];
    int idx[SNEI];
#pragma unroll
    for (int s = 0; s < SNEI; s++) idx[s] = neigh_idx[b * SNEI + s];

    float4 sf = ((const float4*)self_table)[(size_t)node * 32 + lane];
    float4 pr[SNEI];
#pragma unroll
    for (int s = 0; s < SNEI; s++)
        pr[s] = ((const float4*)prod)[(size_t)idx[s] * 32 + lane];
    float pd[SNEI];
#pragma unroll
    for (int s = 0; s < SNEI; s++) pd[s] = pdot[idx[s]];

    float4 al = ((const float4*)alpha)[lane];
    float d = sf.x * al.x + sf.y * al.y + sf.z * al.z + sf.w * al.w;
#pragma unroll
    for (int o = 16; o; o >>= 1) d += __shfl_xor_sync(0xffffffffu, d, o);

    float e[SNEI], sum = 0.f;
#pragma unroll
    for (int s = 0; s < SNEI; s++) {
        float l = fmaxf(d + pd[s], 0.f);
        e[s] = __expf(l);
        sum += e[s];
    }
    float inv = 1.0f / sum;

    float4 agg = make_float4(0.f, 0.f, 0.f, 0.f);
#pragma unroll
    for (int s = 0; s < SNEI; s++) {
        float w = e[s] * inv;
        agg.x = fmaf(w, pr[s].x, agg.x);
        agg.y = fmaf(w, pr[s].y, agg.y);
        agg.z = fmaf(w, pr[s].z, agg.z);
        agg.w = fmaf(w, pr[s].w, agg.w);
    }

    ((float4*)comb)[(size_t)b * 64 + lane]      = sf;
    ((float4*)comb)[(size_t)b * 64 + 32 + lane] = agg;
}

// ---------------------------------------------------------------------------
// GEMM split-K: part[ks][b][e] = comb[b, ks*128:(ks+1)*128] @ W[e, same]^T
// BM=64, BN=128, BK=16, 128 threads, 8x8 f32x2 microtile. grid.y = kslice.
// ---------------------------------------------------------------------------
#define GBM 64
#define GBK 16

__global__ __launch_bounds__(128)
void gemm_part_kernel(const float* __restrict__ A,
                      const float* __restrict__ W,
                      float* __restrict__ part,
                      int Brows)
{
    __shared__ __align__(16) float As[GBK][GBM];
    __shared__ __align__(16) float Bs[GBK][FDIM];

    int tid = threadIdx.x;
    int tx = tid & 15;
    int ty = tid >> 4;
    int row0 = blockIdx.x * GBM;
    int kbase = blockIdx.y * 128;

    ull acc[8][4];
#pragma unroll
    for (int i = 0; i < 8; i++)
#pragma unroll
        for (int p = 0; p < 4; p++) acc[i][p] = 0ull;

    for (int kt = 0; kt < 8; kt++) {
        int k0 = kbase + kt * GBK;
#pragma unroll
        for (int j = 0; j < 2; j++) {
            int i = j * 128 + tid;
            int r = i >> 2, c4 = (i & 3) * 4;
            float4 v = make_float4(0.f, 0.f, 0.f, 0.f);
            if (row0 + r < Brows)
                v = *(const float4*)&A[(size_t)(row0 + r) * 256 + k0 + c4];
            As[c4 + 0][r] = v.x; As[c4 + 1][r] = v.y;
            As[c4 + 2][r] = v.z; As[c4 + 3][r] = v.w;
        }
        {
#pragma unroll
            for (int j = 0; j < 4; j++) {
                float4 v = *(const float4*)&W[(size_t)tid * 256 + k0 + j * 4];
                Bs[j * 4 + 0][tid] = v.x; Bs[j * 4 + 1][tid] = v.y;
                Bs[j * 4 + 2][tid] = v.z; Bs[j * 4 + 3][tid] = v.w;
            }
        }
        __syncthreads();

#pragma unroll
        for (int kk = 0; kk < GBK; kk++) {
            float4 a0 = *(const float4*)&As[kk][ty * 8];
            float4 a1 = *(const float4*)&As[kk][ty * 8 + 4];
            const ull* bp = (const ull*)&Bs[kk][tx * 8];
            ull b0 = bp[0], b1 = bp[1], b2 = bp[2], b3 = bp[3];
            float av[8] = {a0.x, a0.y, a0.z, a0.w, a1.x, a1.y, a1.z, a1.w};
#pragma unroll
            for (int i = 0; i < 8; i++) {
                ull ap;
                PACK2(ap, av[i], av[i]);
                FFMA2(acc[i][0], ap, b0, acc[i][0]);
                FFMA2(acc[i][1], ap, b1, acc[i][1]);
                FFMA2(acc[i][2], ap, b2, acc[i][2]);
                FFMA2(acc[i][3], ap, b3, acc[i][3]);
            }
        }
        __syncthreads();
    }

    float* dst = part + (size_t)blockIdx.y * BMAX * FDIM;
#pragma unroll
    for (int i = 0; i < 8; i++) {
        int r = row0 + ty * 8 + i;
        if (r < Brows) {
            float o[8];
#pragma unroll
            for (int p = 0; p < 4; p++)
                UNPACK2(o[2 * p], o[2 * p + 1], acc[i][p]);
            *(float4*)&dst[(size_t)r * FDIM + tx * 8]     = make_float4(o[0], o[1], o[2], o[3]);
            *(float4*)&dst[(size_t)r * FDIM + tx * 8 + 4] = make_float4(o[4], o[5], o[6], o[7]);
        }
    }
}

// ---------------------------------------------------------------------------
__global__ __launch_bounds__(256)
void combine_kernel(const float* __restrict__ part, float* __restrict__ out, int total4)
{
    int i = blockIdx.x * 256 + threadIdx.x;
    if (i >= total4) return;
    float4 a = ((const float4*)part)[i];
    float4 b = ((const float4*)(part + (size_t)BMAX * FDIM))[i];
    float4 o;
    o.x = fmaxf(a.x + b.x, 0.f);
    o.y = fmaxf(a.y + b.y, 0.f);
    o.z = fmaxf(a.z + b.z, 0.f);
    o.w = fmaxf(a.w + b.w, 0.f);
    ((float4*)out)[i] = o;
}

// ---------------------------------------------------------------------------
extern "C" void kernel_launch(void* const* d_in, const int* in_sizes, int n_in,
                              void* d_out, int out_size)
{
    const int*   nodes      = (const int*)d_in[0];
    const int*   neigh_idx  = (const int*)d_in[1];
    const float* self_table = (const float*)d_in[2];
    const float* neigh_tab  = (const float*)d_in[3];
    const float* center     = (const float*)d_in[4];
    const float* cmask      = (const float*)d_in[5];
    const float* weight     = (const float*)d_in[6];
    const float* alpha      = (const float*)d_in[7];
    float*       out        = (float*)d_out;

    int B = in_sizes[0];
    int N = in_sizes[3] / FDIM;

    float *prod, *pd, *c2, *comb, *part;
    cudaGetSymbolAddress((void**)&prod, g_prod);
    cudaGetSymbolAddress((void**)&pd,   g_pdot);
    cudaGetSymbolAddress((void**)&c2,   g_c2);
    cudaGetSymbolAddress((void**)&comb, g_comb);
    cudaGetSymbolAddress((void**)&part, g_part);

    c2_kernel<<<1, 512>>>(center, c2);
    precompute_kernel<<<(N + 63) / 64, 128>>>(neigh_tab, center, alpha, cmask,
                                              c2, prod, pd, N);
    row_kernel<<<(B + 7) / 8, 256>>>(nodes, neigh_idx, self_table, alpha,
                                     pd, prod, comb, B);
    dim3 gg((B + GBM - 1) / GBM, 2);
    gemm_part_kernel<<<gg, 128>>>(comb, weight, part, B);
    combine_kernel<<<(B * 32 + 255) / 256, 256>>>(part, out, B * 32);
}